// round 17
// baseline (speedup 1.0000x reference)
#include <cuda_runtime.h>

#define BB 2
#define FF 32
#define NN 1024
#define HH 64
#define TI 32
#define TJ 64

// Scratch: [b][hslot][n], hslot 0..63 = Hi (with b1 folded in), 64..127 = Hj
__device__ float g_H[BB * 128 * NN];

__device__ __forceinline__ float sigmoidf_fast(float x) {
    return __fdividef(1.0f, 1.0f + __expf(-x));
}

// packed step: acc2 += max(hid2 + hj2, 0) * w2   (element-wise on f32x2)
#define EDGE_STEP(ACC, HID, HJ2, W2)                                   \
    asm("{\n\t"                                                        \
        ".reg .b64 s;\n\t"                                             \
        ".reg .f32 sl, sh;\n\t"                                        \
        "add.rn.f32x2 s, %1, %2;\n\t"                                  \
        "mov.b64 {sl, sh}, s;\n\t"                                     \
        "max.f32 sl, sl, 0f00000000;\n\t"                              \
        "max.f32 sh, sh, 0f00000000;\n\t"                              \
        "mov.b64 s, {sl, sh};\n\t"                                     \
        "fma.rn.f32x2 %0, s, %3, %0;\n\t"                              \
        "}" : "+l"(ACC) : "l"(HID), "l"(HJ2), "l"(W2))

#define DUP2(D, S)                                                     \
    asm("mov.b64 %0, {%1, %1};" : "=l"(D) : "f"(S))

#define UNPACK2(LO, HI, S)                                             \
    asm("mov.b64 {%0, %1}, %2;" : "=f"(LO), "=f"(HI) : "l"(S))

// ---------------------------------------------------------------------------
// Phase 1: Hi[b,h,n] = sum_f emb[b,f,n]*W1[h,f] + b1[h]
//          Hj[b,h,n] = sum_f emb[b,f,n]*W1[h,F+f]
// 256 blocks x 256 threads (8 warps/block) for latency hiding.
// Block = (b, 8-wide n tile). Thread = hslot(0..127) x n4(0..1), 4 n each.
// ---------------------------------------------------------------------------
__global__ void __launch_bounds__(256) phase1_kernel(
    const float* __restrict__ emb,  // [B][F][N]
    const float* __restrict__ W1,   // [H][2F]
    const float* __restrict__ b1)   // [H]
{
    const int t     = threadIdx.x;
    const int hslot = t & 127;
    const int h     = hslot & 63;
    const int isj   = hslot >> 6;
    const int n4    = t >> 7;           // 0 or 1
    const int blk   = blockIdx.x;
    const int b     = blk / (NN / 8);
    const int n0    = (blk % (NN / 8)) * 8;

    __shared__ float es[FF][8];

    if (t < 64) {
        int f  = t >> 1;
        int nh = t & 1;
        *(float4*)&es[f][nh * 4] =
            *(const float4*)&emb[(b * FF + f) * NN + n0 + nh * 4];
    }

    float w[FF];
    #pragma unroll
    for (int f = 0; f < FF; f++)
        w[f] = W1[h * (2 * FF) + isj * FF + f];
    const float bias = isj ? 0.0f : b1[h];

    __syncthreads();

    float a0 = bias, a1 = bias, a2 = bias, a3 = bias;
    #pragma unroll
    for (int f = 0; f < FF; f++) {
        float4 ev = *(float4*)&es[f][n4 * 4];   // broadcast
        a0 = fmaf(ev.x, w[f], a0);
        a1 = fmaf(ev.y, w[f], a1);
        a2 = fmaf(ev.z, w[f], a2);
        a3 = fmaf(ev.w, w[f], a3);
    }
    float4 r = {a0, a1, a2, a3};
    *(float4*)&g_H[(size_t)(b * 128 + hslot) * NN + n0 + n4 * 4] = r;
}

// ---------------------------------------------------------------------------
// Phase 2: out[b,i,j] = sigmoid( sum_h relu(Hi[b,i,h]+Hj[b,j,h]) * W2[h] + b2 )
// 32x64 (i,j) tile per block, 128 threads, 4i x 4j per thread (j packed f32x2).
// Per warp-h: 3 LDS / 4 wavefronts serve 512 output-units (issue-bound by far).
// smem 24.5KB -> up to 9 blocks/SM (36 warps).
// ---------------------------------------------------------------------------
__global__ void __launch_bounds__(128) phase2_kernel(
    const float* __restrict__ W2,   // [1][H]
    const float* __restrict__ b2,   // [1]
    float* __restrict__ out)        // [B][N][N]
{
    __shared__ __align__(16) float his[HH * TI];               // 8 KB
    __shared__ __align__(16) float hjs[HH * TJ];               // 16 KB
    __shared__ unsigned long long w2d[HH];                     // 512 B

    const int tid = threadIdx.x;
    const int b   = blockIdx.z;
    const int i0  = blockIdx.y * TI;
    const int j0  = blockIdx.x * TJ;
    const int tx  = tid & 15;   // 4 j's (2 packed pairs)
    const int ty  = tid >> 4;   // 4 i's  (ty 0..7)

    const float* HiB = &g_H[(size_t)(b * 128) * NN];
    const float* HjB = &g_H[(size_t)(b * 128 + 64) * NN];

    // his: 64h x 32i = 512 float4, 128 thr -> 4 each
    #pragma unroll
    for (int k = 0; k < 4; k++) {
        int idx = tid + k * 128;
        int hh  = idx >> 3;
        int i4  = (idx & 7) * 4;
        *(float4*)&his[hh * TI + i4] = *(const float4*)&HiB[hh * NN + i0 + i4];
    }
    // hjs: 64h x 64j = 1024 float4, 128 thr -> 8 each
    #pragma unroll
    for (int k = 0; k < 8; k++) {
        int idx = tid + k * 128;
        int hh  = idx >> 4;
        int j4  = (idx & 15) * 4;
        *(float4*)&hjs[hh * TJ + j4] = *(const float4*)&HjB[hh * NN + j0 + j4];
    }
    if (tid < HH) {
        unsigned long long wp;
        DUP2(wp, W2[tid]);
        w2d[tid] = wp;
    }
    __syncthreads();

    unsigned long long acc[4][2] = {};

    const float* hip = &his[ty * 4];
    const float* hjp = &hjs[tx * 4];

    #pragma unroll 8
    for (int h = 0; h < HH; h++) {
        float4 hi4 = *(const float4*)&hip[h * TI];          // LDS.128 (2 addrs/warp)
        ulonglong2 hj = *(const ulonglong2*)&hjp[h * TJ];   // LDS.128 (16 addrs/warp)
        unsigned long long w = w2d[h];                      // LDS.64 broadcast

        unsigned long long hid[4];
        DUP2(hid[0], hi4.x);
        DUP2(hid[1], hi4.y);
        DUP2(hid[2], hi4.z);
        DUP2(hid[3], hi4.w);

        #pragma unroll
        for (int a = 0; a < 4; a++) {
            EDGE_STEP(acc[a][0], hid[a], hj.x, w);
            EDGE_STEP(acc[a][1], hid[a], hj.y, w);
        }
    }

    const float b2v = b2[0];
    #pragma unroll
    for (int a = 0; a < 4; a++) {
        float a0, a1, a2, a3;
        UNPACK2(a0, a1, acc[a][0]);
        UNPACK2(a2, a3, acc[a][1]);
        float4 o;
        o.x = sigmoidf_fast(a0 + b2v);
        o.y = sigmoidf_fast(a1 + b2v);
        o.z = sigmoidf_fast(a2 + b2v);
        o.w = sigmoidf_fast(a3 + b2v);
        size_t row = (size_t)(b * NN + i0 + ty * 4 + a) * NN;
        *(float4*)&out[row + j0 + tx * 4] = o;
    }
}

// ---------------------------------------------------------------------------
// inputs (metadata order): 0=adj_in (unused), 1=emb_in, 2=layer (unused),
//                          3=W1, 4=b1, 5=W2, 6=b2
// ---------------------------------------------------------------------------
extern "C" void kernel_launch(void* const* d_in, const int* in_sizes, int n_in,
                              void* d_out, int out_size)
{
    const float* emb = (const float*)d_in[1];
    const float* W1  = (const float*)d_in[3];
    const float* b1  = (const float*)d_in[4];
    const float* W2  = (const float*)d_in[5];
    const float* b2  = (const float*)d_in[6];
    float* out = (float*)d_out;

    phase1_kernel<<<BB * (NN / 8), 256>>>(emb, W1, b1);

    dim3 grid(NN / TJ, NN / TI, BB);
    phase2_kernel<<<grid, 128>>>(W2, b2, out);
}